// round 15
// baseline (speedup 1.0000x reference)
#include <cuda_runtime.h>
#include <cuda_fp16.h>
#include <cstdint>

#define T_DIM 2048
#define B_DIM 2
#define E_DIM 1024
#define H_DIM 16
#define HD_DIM 64
#define S_DIM 2048
#define MB_DIM (T_DIM * B_DIM)     // 4096
#define LDQ (B_DIM * E_DIM)        // 2048

// Static device scratch
__device__ __half g_xq[(size_t)MB_DIM * E_DIM];
__device__ __half g_xk[(size_t)MB_DIM * E_DIM];
__device__ __half g_xv[(size_t)MB_DIM * E_DIM];
__device__ __half g_wq[(size_t)E_DIM * E_DIM];
__device__ __half g_wk[(size_t)E_DIM * E_DIM];
__device__ __half g_wv[(size_t)E_DIM * E_DIM];
__device__ __half g_wo[(size_t)E_DIM * E_DIM];
__device__ __half g_qh[(size_t)MB_DIM * E_DIM];
__device__ __half g_kh[(size_t)MB_DIM * E_DIM];
__device__ __half g_vh[(size_t)MB_DIM * E_DIM];
__device__ __half g_ctxh[(size_t)MB_DIM * E_DIM];
__device__ __half g_vt[(size_t)B_DIM * H_DIM * HD_DIM * S_DIM];
__device__ __half g_ptil[(size_t)B_DIM * H_DIM * T_DIM * S_DIM];  // unnormalized exp scores
__device__ float  g_zinv[(size_t)B_DIM * H_DIM * T_DIM];          // per-row 1/Z

__device__ __forceinline__ uint32_t smem_u32(const void* p) {
    uint32_t a;
    asm("{ .reg .u64 t; cvta.to.shared.u64 t, %1; cvt.u32.u64 %0, t; }" : "=r"(a) : "l"(p));
    return a;
}
__device__ __forceinline__ void cp16(uint32_t dst, const void* src) {
    asm volatile("cp.async.ca.shared.global [%0], [%1], 16;" :: "r"(dst), "l"(src) : "memory");
}
#define CP_COMMIT() asm volatile("cp.async.commit_group;" ::: "memory")
#define CP_WAIT1()  asm volatile("cp.async.wait_group 1;" ::: "memory")
#define CP_WAIT0()  asm volatile("cp.async.wait_group 0;" ::: "memory")

__device__ __forceinline__ void ldm_x4(uint32_t r[4], uint32_t a) {
    asm volatile("ldmatrix.sync.aligned.m8n8.x4.shared.b16 {%0,%1,%2,%3}, [%4];"
        : "=r"(r[0]), "=r"(r[1]), "=r"(r[2]), "=r"(r[3]) : "r"(a));
}
__device__ __forceinline__ void mma_f16(float c[4], const uint32_t a[4], const uint32_t b[2]) {
    asm volatile(
        "mma.sync.aligned.m16n8k16.row.col.f32.f16.f16.f32 "
        "{%0,%1,%2,%3}, {%4,%5,%6,%7}, {%8,%9}, {%0,%1,%2,%3};"
        : "+f"(c[0]), "+f"(c[1]), "+f"(c[2]), "+f"(c[3])
        : "r"(a[0]), "r"(a[1]), "r"(a[2]), "r"(a[3]), "r"(b[0]), "r"(b[1]));
}
// ex2.approx.f32 — MUFU.EX2
__device__ __forceinline__ float ex2(float x) {
    float r;
    asm("ex2.approx.f32 %0, %1;" : "=f"(r) : "f"(x));
    return r;
}
__device__ __forceinline__ uint32_t packh2(float a, float b) {
    union { __half2 h; uint32_t u; } p;
    p.h = __floats2half2_rn(a, b);
    return p.u;
}

// ---------------------------------------------------------------------------
// fp16 mma.sync GEMM core (projections). CMODE 0: fp32 out; 1: fp16 out.
// ---------------------------------------------------------------------------
template <int BN, int WARPS_M, int WARPS_N, int CMODE>
__device__ __forceinline__ void mm_core(
    const __half* __restrict__ A, int lda,
    const __half* __restrict__ B, int ldb,
    void* Cp, int ldc,
    const float* __restrict__ bias, float alpha, int K,
    int m0, int n0)
{
    constexpr int BM = 128, BK = 64, PAD = 72;
    constexpr int WM = BM / WARPS_M, WN = BN / WARPS_N;
    constexpr int MF = WM / 16, NF = WN / 8;
    constexpr int NCA = (BM * BK / 8) / 256;
    constexpr int NCB = (BN * BK / 8) / 256;
    constexpr uint32_t ASTG = BM * PAD * 2;
    constexpr uint32_t BSTG = BN * PAD * 2;
    constexpr uint32_t STG  = ASTG + BSTG;

    extern __shared__ __align__(16) char dsm[];

    const int tid = threadIdx.x;
    const int wid = tid >> 5;
    const int lane = tid & 31;
    const int lr = lane >> 2;
    const int lc = lane & 3;
    const int warpM = wid % WARPS_M;
    const int warpN = wid / WARPS_M;

    const uint32_t smb = smem_u32(dsm);

    float acc[MF][NF][4];
#pragma unroll
    for (int i = 0; i < MF; i++)
#pragma unroll
        for (int j = 0; j < NF; j++)
#pragma unroll
            for (int q = 0; q < 4; q++) acc[i][j][q] = 0.f;

    auto ldgsts = [&](int kt, int p) {
        const int k0 = kt * BK;
        const uint32_t ab = smb + (uint32_t)p * STG;
        const uint32_t bb = ab + ASTG;
#pragma unroll
        for (int i = 0; i < NCA; i++) {
            int ch = tid + i * 256, r = ch >> 3, c = (ch & 7) * 8;
            cp16(ab + (uint32_t)(r * PAD + c) * 2,
                 A + (size_t)(m0 + r) * lda + k0 + c);
        }
#pragma unroll
        for (int i = 0; i < NCB; i++) {
            int ch = tid + i * 256, r = ch >> 3, c = (ch & 7) * 8;
            cp16(bb + (uint32_t)(r * PAD + c) * 2,
                 B + (size_t)(n0 + r) * ldb + k0 + c);
        }
    };

    auto compute = [&](int p) {
        const uint32_t ab = smb + (uint32_t)p * STG;
        const uint32_t bb = ab + ASTG;
#pragma unroll
        for (int ks = 0; ks < BK / 16; ks++) {
            const int kh = ks * 16;
            uint32_t af[MF][4], bf[NF][2];
#pragma unroll
            for (int i = 0; i < MF; i++) {
                uint32_t off = (uint32_t)((warpM * WM + i * 16 + (lane & 15)) * PAD +
                                          kh + ((lane >> 4) << 3));
                ldm_x4(af[i], ab + (off << 1));
            }
#pragma unroll
            for (int j = 0; j < NF; j += 2) {
                int row = warpN * WN + (j + (lane >> 4)) * 8 + (lane & 7);
                int col = kh + ((lane >> 3) & 1) * 8;
                uint32_t r4[4];
                ldm_x4(r4, bb + ((uint32_t)(row * PAD + col) << 1));
                bf[j][0] = r4[0]; bf[j][1] = r4[1];
                bf[j + 1][0] = r4[2]; bf[j + 1][1] = r4[3];
            }
#pragma unroll
            for (int i = 0; i < MF; i++)
#pragma unroll
                for (int j = 0; j < NF; j++)
                    mma_f16(acc[i][j], af[i], bf[j]);
        }
    };

    const int ktiles = K / BK;
    ldgsts(0, 0);
    CP_COMMIT();
    if (ktiles > 1) ldgsts(1, 1);
    CP_COMMIT();
    for (int kt = 0; kt < ktiles; kt++) {
        if (kt + 1 < ktiles) { CP_WAIT1(); } else { CP_WAIT0(); }
        __syncthreads();
        if (kt + 2 < ktiles) ldgsts(kt + 2, (kt + 2) % 3);
        CP_COMMIT();
        compute(kt % 3);
    }

#pragma unroll
    for (int i = 0; i < MF; i++) {
        int r0 = m0 + warpM * WM + i * 16 + lr;
#pragma unroll
        for (int j = 0; j < NF; j++) {
            int c0 = n0 + warpN * WN + j * 8 + 2 * lc;
            float2 bv = bias ? *(const float2*)(bias + c0) : make_float2(0.f, 0.f);
            float x0 = acc[i][j][0] * alpha + bv.x;
            float x1 = acc[i][j][1] * alpha + bv.y;
            float x2 = acc[i][j][2] * alpha + bv.x;
            float x3 = acc[i][j][3] * alpha + bv.y;
            if constexpr (CMODE == 1) {
                __half* C = (__half*)Cp;
                *(__half2*)(C + (size_t)r0 * ldc + c0) = __floats2half2_rn(x0, x1);
                *(__half2*)(C + (size_t)(r0 + 8) * ldc + c0) = __floats2half2_rn(x2, x3);
            } else {
                float* C = (float*)Cp;
                *(float2*)(C + (size_t)r0 * ldc + c0) = make_float2(x0, x1);
                *(float2*)(C + (size_t)(r0 + 8) * ldc + c0) = make_float2(x2, x3);
            }
        }
    }
}

// ---------------- projection wrappers ----------------
__global__ void __launch_bounds__(256, 2) k_proj3(
    const __half* __restrict__ xq, const __half* __restrict__ xk, const __half* __restrict__ xv,
    const __half* __restrict__ wq, const __half* __restrict__ wk, const __half* __restrict__ wv,
    const float* __restrict__ bq, const float* __restrict__ bk, const float* __restrict__ bv,
    __half* __restrict__ qh, __half* __restrict__ kh, __half* __restrict__ vh)
{
    const __half* A; const __half* W; const float* bias; __half* C;
    if (blockIdx.z == 0)      { A = xq; W = wq; bias = bq; C = qh; }
    else if (blockIdx.z == 1) { A = xk; W = wk; bias = bk; C = kh; }
    else                      { A = xv; W = wv; bias = bv; C = vh; }
    mm_core<128, 2, 4, 1>(A, E_DIM, W, E_DIM, C, E_DIM, bias, 1.f, E_DIM,
                          blockIdx.y * 128, blockIdx.x * 128);
}

// ---------------------------------------------------------------------------
// Merged final wave: proj blocks + avg blocks (independent, overlapped).
// ---------------------------------------------------------------------------
#define NPROJ 256   // (E/128) * (MB/128)

__global__ void __launch_bounds__(256, 2) k_avg_proj(
    const __half* __restrict__ ctxh, const __half* __restrict__ wo,
    const float* __restrict__ bo, float* __restrict__ out,
    const __half* __restrict__ ptil, const float* __restrict__ zinv,
    float* __restrict__ avgw)
{
    const int bidx = blockIdx.x;
    if (bidx < NPROJ) {
        mm_core<128, 2, 4, 0>(ctxh, E_DIM, wo, E_DIM, out, E_DIM, bo, 1.f, E_DIM,
                              (bidx >> 3) * 128, (bidx & 7) * 128);
        return;
    }

    const int j = bidx - NPROJ;
    const int t = j & (T_DIM - 1);
    const int b = j >> 11;
    const int tid = threadIdx.x;

    float inv[H_DIM];
#pragma unroll
    for (int h = 0; h < H_DIM; h++)
        inv[h] = __ldg(zinv + (size_t)(b * H_DIM + h) * T_DIM + t);

    float acc[8];
#pragma unroll
    for (int i = 0; i < 8; i++) acc[i] = 0.f;

    uint4 u[H_DIM];
#pragma unroll
    for (int h = 0; h < H_DIM; h++)
        u[h] = *(const uint4*)(ptil + ((size_t)(b * H_DIM + h) * T_DIM + t) * S_DIM + tid * 8);

#pragma unroll
    for (int h = 0; h < H_DIM; h++) {
        const __half2* hp = (const __half2*)&u[h];
#pragma unroll
        for (int q = 0; q < 4; q++) {
            float2 f = __half22float2(hp[q]);
            acc[2 * q]     += f.x * inv[h];
            acc[2 * q + 1] += f.y * inv[h];
        }
    }

    const float invH = 1.f / (float)H_DIM;
    float* arow = avgw + ((size_t)b * T_DIM + t) * S_DIM + tid * 8;
    float4 o0 = {acc[0] * invH, acc[1] * invH, acc[2] * invH, acc[3] * invH};
    float4 o1 = {acc[4] * invH, acc[5] * invH, acc[6] * invH, acc[7] * invH};
    *(float4*)(arow) = o0;
    *(float4*)(arow + 4) = o1;
}

// ---------------------------------------------------------------------------
// Fused attention v3: QK^T + exp + Z + (p~ @ V) with register-resident P
// fragments (mma1 C-frag == mma2 A-frag identity). One sync per chunk,
// P smem double-buffered only for the coalesced gmem store of p~.
// 256 threads = 8 warps, warpM=4 x warpN=2. 32 s-chunks of 64.
// ---------------------------------------------------------------------------
#define ACH 64
#define NCHK (S_DIM / ACH)     // 32
#define QOFF 0
#define QSZ  (128 * 72 * 2)            // 18432
#define KOFF QSZ                        // 18432
#define KSZ  (64 * 72 * 2)             // 9216 per buf, 3 bufs
#define VOFF (KOFF + 3 * KSZ)          // 46080
#define VSZ  (64 * 72 * 2)             // 9216 per buf, 3 bufs
#define POFF (VOFF + 3 * VSZ)          // 73728
#define PSZ  (128 * 72 * 2)            // 18432 per buf, 2 bufs
#define SM_ATTN (POFF + 2 * PSZ)       // 110592
// epilogue aliases (Q/K area is dead by then)
#define XPITCH 66
#define ZROFF  (128 * XPITCH * 4)      // 33792; zred float[128][2] -> ends 34816 < 46080

#define EXP2_SCALE 0.18033688011112042f

__global__ void __launch_bounds__(256, 2) k_attn(
    const __half* __restrict__ qh, const __half* __restrict__ kh,
    const __half* __restrict__ vt, __half* __restrict__ ptil,
    float* __restrict__ zinv, __half* __restrict__ ctx)
{
    extern __shared__ __align__(16) char dsm[];
    const uint32_t smb = smem_u32(dsm);

    const int tid = threadIdx.x;
    const int wid = tid >> 5;
    const int lane = tid & 31;
    const int lr = lane >> 2, lc = lane & 3;
    const int warpM = wid & 3;            // 4
    const int warpN = wid >> 2;           // 2
    const int z  = blockIdx.x;
    const int t0 = blockIdx.y * 128;
    const int b = z >> 4, h = z & 15;

    const __half* qptr = qh + (size_t)b * E_DIM + h * HD_DIM;
    const __half* kptr = kh + (size_t)b * E_DIM + h * HD_DIM;
    const __half* vptr = vt + (size_t)z * HD_DIM * S_DIM;
    __half* pout = ptil + ((size_t)z * T_DIM + t0) * S_DIM;

    auto ldgK = [&](int c) {
        const int s0 = c * ACH;
        const uint32_t kb = smb + KOFF + (uint32_t)(c % 3) * KSZ;
#pragma unroll
        for (int i = 0; i < 2; i++) {
            int ch = tid + i * 256, r = ch >> 3, cc = (ch & 7) * 8;
            cp16(kb + (uint32_t)(r * 72 + cc) * 2,
                 kptr + (size_t)(s0 + r) * LDQ + cc);
        }
    };
    auto ldgV = [&](int c) {
        const int s0 = c * ACH;
        const uint32_t vb = smb + VOFF + (uint32_t)(c % 3) * VSZ;
#pragma unroll
        for (int i = 0; i < 2; i++) {
            int ch = tid + i * 256, r = ch >> 3, cc = (ch & 7) * 8;
            cp16(vb + (uint32_t)(r * 72 + cc) * 2,
                 vptr + (size_t)r * S_DIM + s0 + cc);
        }
    };
    auto storeP = [&](int c) {   // coalesced gmem store of chunk c from P[c&1]
        const uint32_t pb = smb + POFF + (uint32_t)(c & 1) * PSZ;
        const int s0 = c * ACH;
#pragma unroll
        for (int i = 0; i < 4; i++) {
            int idx = tid + i * 256;
            int row = idx >> 3, col8 = (idx & 7) * 8;
            uint4 v;
            asm volatile("ld.shared.v4.u32 {%0,%1,%2,%3}, [%4];"
                : "=r"(v.x), "=r"(v.y), "=r"(v.z), "=r"(v.w)
                : "r"(pb + (uint32_t)(row * 72 + col8) * 2));
            *(uint4*)(pout + (size_t)row * S_DIM + s0 + col8) = v;
        }
    };

#pragma unroll
    for (int i = 0; i < 4; i++) {
        int ch = tid + i * 256, r = ch >> 3, cc = (ch & 7) * 8;
        cp16(smb + QOFF + (uint32_t)(r * 72 + cc) * 2,
             qptr + (size_t)(t0 + r) * LDQ + cc);
    }
    ldgK(0); ldgV(0);
    CP_COMMIT();
    ldgK(1); ldgV(1);
    CP_COMMIT();

    uint32_t afq[4][2][4];
    float acc2[2][8][4];
#pragma unroll
    for (int i = 0; i < 2; i++)
#pragma unroll
        for (int j = 0; j < 8; j++)
#pragma unroll
            for (int q = 0; q < 4; q++) acc2[i][j][q] = 0.f;
    float z0[2] = {0.f, 0.f}, z1[2] = {0.f, 0.f};

    for (int c = 0; c < NCHK; c++) {
        if (c + 1 < NCHK) { CP_WAIT1(); } else { CP_WAIT0(); }
        __syncthreads();

        if (c == 0) {
#pragma unroll
            for (int ks = 0; ks < 4; ks++)
#pragma unroll
                for (int i = 0; i < 2; i++) {
                    uint32_t off = (uint32_t)((warpM * 32 + i * 16 + (lane & 15)) * 72 +
                                              ks * 16 + ((lane >> 4) << 3));
                    ldm_x4(afq[ks][i], smb + QOFF + (off << 1));
                }
        } else {
            storeP(c - 1);    // reads P[(c-1)&1], ordered by the sync above
        }

        if (c + 2 < NCHK) { ldgK(c + 2); ldgV(c + 2); }
        CP_COMMIT();

        const uint32_t kb = smb + KOFF + (uint32_t)(c % 3) * KSZ;
        const uint32_t vb = smb + VOFF + (uint32_t)(c % 3) * VSZ;
        const uint32_t pb = smb + POFF + (uint32_t)(c & 1) * PSZ;

        // ---- mma1: q[32 x 64] @ K^T -> acc1[32 x 32(s-half)] per warp ----
        float acc1[2][4][4];
#pragma unroll
        for (int i = 0; i < 2; i++)
#pragma unroll
            for (int j = 0; j < 4; j++)
#pragma unroll
                for (int q = 0; q < 4; q++) acc1[i][j][q] = 0.f;

#pragma unroll
        for (int ks = 0; ks < 4; ks++) {
            const int khc = ks * 16;
            uint32_t bf[4][2];
#pragma unroll
            for (int j = 0; j < 4; j += 2) {
                int row = warpN * 32 + (j + (lane >> 4)) * 8 + (lane & 7);
                int col = khc + ((lane >> 3) & 1) * 8;
                uint32_t r4[4];
                ldm_x4(r4, kb + ((uint32_t)(row * 72 + col) << 1));
                bf[j][0] = r4[0]; bf[j][1] = r4[1];
                bf[j + 1][0] = r4[2]; bf[j + 1][1] = r4[3];
            }
#pragma unroll
            for (int i = 0; i < 2; i++)
#pragma unroll
                for (int j = 0; j < 4; j++)
                    mma_f16(acc1[i][j], afq[ks][i], bf[j]);
        }

        // ---- exp + Z + pack to A-frags (regs) + STS for gmem staging ----
        uint32_t afp[2][2][4];
#pragma unroll
        for (int i = 0; i < 2; i++) {
            int rl0 = warpM * 32 + i * 16 + lr;
#pragma unroll
            for (int j = 0; j < 4; j++) {
                int c0 = warpN * 32 + j * 8 + 2 * lc;
                float x0 = ex2(acc1[i][j][0] * EXP2_SCALE);
                float x1 = ex2(acc1[i][j][1] * EXP2_SCALE);
                float x2 = ex2(acc1[i][j][2] * EXP2_SCALE);
                float x3 = ex2(acc1[i][j][3] * EXP2_SCALE);
                z0[i] += x0 + x1;
                z1[i] += x2 + x3;
                uint32_t h01 = packh2(x0, x1);
                uint32_t h23 = packh2(x2, x3);
                const int k2 = j >> 1, half = (j & 1) * 2;
                afp[i][k2][half + 0] = h01;
                afp[i][k2][half + 1] = h23;
                *(uint32_t*)(dsm + (pb - smb) + (uint32_t)(rl0 * 72 + c0) * 2) = h01;
                *(uint32_t*)(dsm + (pb - smb) + (uint32_t)((rl0 + 8) * 72 + c0) * 2) = h23;
            }
        }

        // ---- mma2: p-frags (regs) @ V^T -> acc2 partial over this s-half ----
#pragma unroll
        for (int k = 0; k < 2; k++) {
            const int scol = warpN * 32 + k * 16;
            uint32_t bf2[8][2];
#pragma unroll
            for (int j = 0; j < 8; j += 2) {
                int row = (j + (lane >> 4)) * 8 + (lane & 7);   // d index
                int col = scol + ((lane >> 3) & 1) * 8;          // s index
                uint32_t r4[4];
                ldm_x4(r4, vb + ((uint32_t)(row * 72 + col) << 1));
                bf2[j][0] = r4[0]; bf2[j][1] = r4[1];
                bf2[j + 1][0] = r4[2]; bf2[j + 1][1] = r4[3];
            }
#pragma unroll
            for (int i = 0; i < 2; i++)
#pragma unroll
                for (int j = 0; j < 8; j++)
                    mma_f16(acc2[i][j], afp[i][k], bf2[j]);
        }
    }

    __syncthreads();
    storeP(NCHK - 1);

    // ---- Z: quad reduce then cross-warpN via smem ----
#pragma unroll
    for (int i = 0; i < 2; i++) {
        z0[i] += __shfl_xor_sync(0xffffffffu, z0[i], 1);
        z0[i] += __shfl_xor_sync(0xffffffffu, z0[i], 2);
        z1[i] += __shfl_xor_sync(0xffffffffu, z1[i], 1);
        z1[i] += __shfl_xor_sync(0xffffffffu, z1[i], 2);
    }
    float* zr = (float*)(dsm + ZROFF);
    float* xch = (float*)(dsm);
    if (lc == 0) {
#pragma unroll
        for (int i = 0; i < 2; i++) {
            int rl0 = warpM * 32 + i * 16 + lr;
            zr[rl0 * 2 + warpN] = z0[i];
            zr[(rl0 + 8) * 2 + warpN] = z1[i];
        }
    }
    // warpN==1 exports acc2 partials
    if (warpN == 1) {
#pragma unroll
        for (int i = 0; i < 2; i++) {
            int rl0 = warpM * 32 + i * 16 + lr;
#pragma unroll
            for (int j = 0; j < 8; j++) {
                int c0 = j * 8 + 2 * lc;
                xch[rl0 * XPITCH + c0]       = acc2[i][j][0];
                xch[rl0 * XPITCH + c0 + 1]   = acc2[i][j][1];
                xch[(rl0 + 8) * XPITCH + c0]     = acc2[i][j][2];
                xch[(rl0 + 8) * XPITCH + c0 + 1] = acc2[i][j][3];
            }
        }
    }
    __syncthreads();

    if (tid < 128) {
        float Z = zr[tid * 2] + zr[tid * 2 + 1];
        zinv[(size_t)z * T_DIM + t0 + tid] = 1.f / Z;
    }

    if (warpN == 0) {
#pragma unroll
        for (int i = 0; i < 2; i++) {
            int rl0 = warpM * 32 + i * 16 + lr;
            float inv0 = 1.f / (zr[rl0 * 2] + zr[rl0 * 2 + 1]);
            float inv1 = 1.f / (zr[(rl0 + 8) * 2] + zr[(rl0 + 8) * 2 + 1]);
#pragma unroll
            for (int j = 0; j < 8; j++) {
                int c0 = j * 8 + 2 * lc;
                float v0 = (acc2[i][j][0] + xch[rl0 * XPITCH + c0])     * inv0;
                float v1 = (acc2[i][j][1] + xch[rl0 * XPITCH + c0 + 1]) * inv0;
                float v2 = (acc2[i][j][2] + xch[(rl0 + 8) * XPITCH + c0])     * inv1;
                float v3 = (acc2[i][j][3] + xch[(rl0 + 8) * XPITCH + c0 + 1]) * inv1;
                __half* d0 = ctx + ((size_t)(t0 + rl0) * B_DIM + b) * E_DIM + h * HD_DIM + c0;
                __half* d1 = ctx + ((size_t)(t0 + rl0 + 8) * B_DIM + b) * E_DIM + h * HD_DIM + c0;
                *(__half2*)d0 = __floats2half2_rn(v0, v1);
                *(__half2*)d1 = __floats2half2_rn(v2, v3);
            }
        }
    }
}

// ---------------- single batched fp32 -> fp16 convert (7 tensors) ----------
__global__ void __launch_bounds__(256) k_cvt7(
    const float* __restrict__ i0, const float* __restrict__ i1, const float* __restrict__ i2,
    const float* __restrict__ w0, const float* __restrict__ w1,
    const float* __restrict__ w2, const float* __restrict__ w3,
    __half* __restrict__ o0, __half* __restrict__ o1, __half* __restrict__ o2,
    __half* __restrict__ p0, __half* __restrict__ p1,
    __half* __restrict__ p2, __half* __restrict__ p3,
    int n_in, int n_w)
{
    const float* x; __half* y; int n;
    switch (blockIdx.z) {
        case 0: x = i0; y = o0; n = n_in; break;
        case 1: x = i1; y = o1; n = n_in; break;
        case 2: x = i2; y = o2; n = n_in; break;
        case 3: x = w0; y = p0; n = n_w; break;
        case 4: x = w1; y = p1; n = n_w; break;
        case 5: x = w2; y = p2; n = n_w; break;
        default: x = w3; y = p3; n = n_w; break;
    }
    int i = (blockIdx.x * 256 + threadIdx.x) * 8;
    if (i < n) {
        float4 v0 = *(const float4*)(x + i);
        float4 v1 = *(const float4*)(x + i + 4);
        union { __half2 h[4]; uint4 u; } p;
        p.h[0] = __floats2half2_rn(v0.x, v0.y);
        p.h[1] = __floats2half2_rn(v0.z, v0.w);
        p.h[2] = __floats2half2_rn(v1.x, v1.y);
        p.h[3] = __floats2half2_rn(v1.z, v1.w);
        *(uint4*)(y + i) = p.u;
    }
}

// V transpose fp16
__global__ void __launch_bounds__(256) k_transpose_v(
    const __half* __restrict__ v, __half* __restrict__ vt)
{
    __shared__ __half t[32][34];
    int z = blockIdx.z, b = z >> 4, h = z & 15;
    int s0 = blockIdx.x * 32, d0 = blockIdx.y * 32;
    int lx = threadIdx.x & 31, ly = threadIdx.x >> 5;
#pragma unroll
    for (int i = 0; i < 32; i += 8) {
        int s = s0 + ly + i;
        t[ly + i][lx] = v[(size_t)(s * B_DIM + b) * E_DIM + h * HD_DIM + d0 + lx];
    }
    __syncthreads();
#pragma unroll
    for (int i = 0; i < 32; i += 8) {
        int d = d0 + ly + i;
        vt[((size_t)z * HD_DIM + d) * S_DIM + s0 + lx] = t[lx][ly + i];
    }
}

// ---------------------------------------------------------------------------
extern "C" void kernel_launch(void* const* d_in, const int* in_sizes, int n_in,
                              void* d_out, int out_size)
{
    const float* query = (const float*)d_in[0];
    const float* key   = (const float*)d_in[1];
    const float* value = (const float*)d_in[2];
    const float* Wq = (const float*)d_in[3];
    const float* bq = (const float*)d_in[4];
    const float* Wk = (const float*)d_in[5];
    const float* bk = (const float*)d_in[6];
    const float* Wv = (const float*)d_in[7];
    const float* bv = (const float*)d_in[8];
    const float* Wo = (const float*)d_in[9];
    const float* bo = (const float*)d_in[10];

    float* out  = (float*)d_out;
    float* avgw = out + (size_t)MB_DIM * E_DIM;

    __half *xq, *xk, *xv, *wq, *wk, *wv, *wo, *qh, *kh, *vh, *ctxh, *vt, *pt;
    float *zi;
    cudaGetSymbolAddress((void**)&xq,   g_xq);
    cudaGetSymbolAddress((void**)&xk,   g_xk);
    cudaGetSymbolAddress((void**)&xv,   g_xv);
    cudaGetSymbolAddress((void**)&wq,   g_wq);
    cudaGetSymbolAddress((void**)&wk,   g_wk);
    cudaGetSymbolAddress((void**)&wv,   g_wv);
    cudaGetSymbolAddress((void**)&wo,   g_wo);
    cudaGetSymbolAddress((void**)&qh,   g_qh);
    cudaGetSymbolAddress((void**)&kh,   g_kh);
    cudaGetSymbolAddress((void**)&vh,   g_vh);
    cudaGetSymbolAddress((void**)&ctxh, g_ctxh);
    cudaGetSymbolAddress((void**)&vt,   g_vt);
    cudaGetSymbolAddress((void**)&pt,   g_ptil);
    cudaGetSymbolAddress((void**)&zi,   g_zinv);

    const int SM_P3 = 3 * (128 + 128) * 72 * 2;   // 110592
    cudaFuncSetAttribute(k_proj3,    cudaFuncAttributeMaxDynamicSharedMemorySize, SM_P3);
    cudaFuncSetAttribute(k_avg_proj, cudaFuncAttributeMaxDynamicSharedMemorySize, SM_P3);
    cudaFuncSetAttribute(k_attn,     cudaFuncAttributeMaxDynamicSharedMemorySize, SM_ATTN);

    const int NXE = MB_DIM * E_DIM;   // 4M
    const int NWW = E_DIM * E_DIM;    // 1M
    dim3 gc(NXE / 2048, 1, 7);
    k_cvt7<<<gc, 256>>>(query, key, value, Wq, Wk, Wv, Wo,
                        xq, xk, xv, wq, wk, wv, wo, NXE, NWW);

    dim3 gp3(E_DIM / 128, MB_DIM / 128, 3);             // (8, 32, 3)
    k_proj3<<<gp3, 256, SM_P3>>>(xq, xk, xv, wq, wk, wv, bq, bk, bv, qh, kh, vh);

    dim3 gt(S_DIM / 32, HD_DIM / 32, B_DIM * H_DIM);    // (64, 2, 32)
    k_transpose_v<<<gt, 256>>>(vh, vt);

    dim3 gat(B_DIM * H_DIM, T_DIM / 128);               // (32, 16)
    k_attn<<<gat, 256, SM_ATTN>>>(qh, kh, vt, pt, zi, ctxh);

    k_avg_proj<<<NPROJ + MB_DIM, 256, SM_P3>>>(ctxh, wo, bo, out, pt, zi, avgw);
}

// round 16
// speedup vs baseline: 1.1909x; 1.1909x over previous
#include <cuda_runtime.h>
#include <cuda_fp16.h>
#include <cstdint>

#define T_DIM 2048
#define B_DIM 2
#define E_DIM 1024
#define H_DIM 16
#define HD_DIM 64
#define S_DIM 2048
#define MB_DIM (T_DIM * B_DIM)     // 4096
#define LDQ (B_DIM * E_DIM)        // 2048

// Static device scratch
__device__ __half g_xq[(size_t)MB_DIM * E_DIM];
__device__ __half g_xk[(size_t)MB_DIM * E_DIM];
__device__ __half g_xv[(size_t)MB_DIM * E_DIM];
__device__ __half g_wq[(size_t)E_DIM * E_DIM];
__device__ __half g_wk[(size_t)E_DIM * E_DIM];
__device__ __half g_wv[(size_t)E_DIM * E_DIM];
__device__ __half g_wo[(size_t)E_DIM * E_DIM];
__device__ __half g_qh[(size_t)MB_DIM * E_DIM];
__device__ __half g_kh[(size_t)MB_DIM * E_DIM];
__device__ __half g_vh[(size_t)MB_DIM * E_DIM];
__device__ __half g_ctxh[(size_t)MB_DIM * E_DIM];
__device__ __half g_vt[(size_t)B_DIM * H_DIM * HD_DIM * S_DIM];
__device__ __half g_ptil[(size_t)B_DIM * H_DIM * T_DIM * S_DIM];  // unnormalized exp scores
__device__ float  g_zinv[(size_t)B_DIM * H_DIM * T_DIM];          // per-row 1/Z

__device__ __forceinline__ uint32_t smem_u32(const void* p) {
    uint32_t a;
    asm("{ .reg .u64 t; cvta.to.shared.u64 t, %1; cvt.u32.u64 %0, t; }" : "=r"(a) : "l"(p));
    return a;
}
__device__ __forceinline__ void cp16(uint32_t dst, const void* src) {
    asm volatile("cp.async.ca.shared.global [%0], [%1], 16;" :: "r"(dst), "l"(src) : "memory");
}
#define CP_COMMIT() asm volatile("cp.async.commit_group;" ::: "memory")
#define CP_WAIT1()  asm volatile("cp.async.wait_group 1;" ::: "memory")
#define CP_WAIT0()  asm volatile("cp.async.wait_group 0;" ::: "memory")

__device__ __forceinline__ void ldm_x4(uint32_t r[4], uint32_t a) {
    asm volatile("ldmatrix.sync.aligned.m8n8.x4.shared.b16 {%0,%1,%2,%3}, [%4];"
        : "=r"(r[0]), "=r"(r[1]), "=r"(r[2]), "=r"(r[3]) : "r"(a));
}
__device__ __forceinline__ void mma_f16(float c[4], const uint32_t a[4], const uint32_t b[2]) {
    asm volatile(
        "mma.sync.aligned.m16n8k16.row.col.f32.f16.f16.f32 "
        "{%0,%1,%2,%3}, {%4,%5,%6,%7}, {%8,%9}, {%0,%1,%2,%3};"
        : "+f"(c[0]), "+f"(c[1]), "+f"(c[2]), "+f"(c[3])
        : "r"(a[0]), "r"(a[1]), "r"(a[2]), "r"(a[3]), "r"(b[0]), "r"(b[1]));
}
// ex2.approx.f32 — MUFU.EX2
__device__ __forceinline__ float ex2(float x) {
    float r;
    asm("ex2.approx.f32 %0, %1;" : "=f"(r) : "f"(x));
    return r;
}

// ---------------------------------------------------------------------------
// fp16 mma.sync GEMM core (projections). CMODE 0: fp32 out; 1: fp16 out.
// ---------------------------------------------------------------------------
template <int BN, int WARPS_M, int WARPS_N, int CMODE>
__device__ __forceinline__ void mm_core(
    const __half* __restrict__ A, int lda,
    const __half* __restrict__ B, int ldb,
    void* Cp, int ldc,
    const float* __restrict__ bias, float alpha, int K,
    int m0, int n0)
{
    constexpr int BM = 128, BK = 64, PAD = 72;
    constexpr int WM = BM / WARPS_M, WN = BN / WARPS_N;
    constexpr int MF = WM / 16, NF = WN / 8;
    constexpr int NCA = (BM * BK / 8) / 256;
    constexpr int NCB = (BN * BK / 8) / 256;
    constexpr uint32_t ASTG = BM * PAD * 2;
    constexpr uint32_t BSTG = BN * PAD * 2;
    constexpr uint32_t STG  = ASTG + BSTG;

    extern __shared__ __align__(16) char dsm[];

    const int tid = threadIdx.x;
    const int wid = tid >> 5;
    const int lane = tid & 31;
    const int lr = lane >> 2;
    const int lc = lane & 3;
    const int warpM = wid % WARPS_M;
    const int warpN = wid / WARPS_M;

    const uint32_t smb = smem_u32(dsm);

    float acc[MF][NF][4];
#pragma unroll
    for (int i = 0; i < MF; i++)
#pragma unroll
        for (int j = 0; j < NF; j++)
#pragma unroll
            for (int q = 0; q < 4; q++) acc[i][j][q] = 0.f;

    auto ldgsts = [&](int kt, int p) {
        const int k0 = kt * BK;
        const uint32_t ab = smb + (uint32_t)p * STG;
        const uint32_t bb = ab + ASTG;
#pragma unroll
        for (int i = 0; i < NCA; i++) {
            int ch = tid + i * 256, r = ch >> 3, c = (ch & 7) * 8;
            cp16(ab + (uint32_t)(r * PAD + c) * 2,
                 A + (size_t)(m0 + r) * lda + k0 + c);
        }
#pragma unroll
        for (int i = 0; i < NCB; i++) {
            int ch = tid + i * 256, r = ch >> 3, c = (ch & 7) * 8;
            cp16(bb + (uint32_t)(r * PAD + c) * 2,
                 B + (size_t)(n0 + r) * ldb + k0 + c);
        }
    };

    auto compute = [&](int p) {
        const uint32_t ab = smb + (uint32_t)p * STG;
        const uint32_t bb = ab + ASTG;
#pragma unroll
        for (int ks = 0; ks < BK / 16; ks++) {
            const int kh = ks * 16;
            uint32_t af[MF][4], bf[NF][2];
#pragma unroll
            for (int i = 0; i < MF; i++) {
                uint32_t off = (uint32_t)((warpM * WM + i * 16 + (lane & 15)) * PAD +
                                          kh + ((lane >> 4) << 3));
                ldm_x4(af[i], ab + (off << 1));
            }
#pragma unroll
            for (int j = 0; j < NF; j += 2) {
                int row = warpN * WN + (j + (lane >> 4)) * 8 + (lane & 7);
                int col = kh + ((lane >> 3) & 1) * 8;
                uint32_t r4[4];
                ldm_x4(r4, bb + ((uint32_t)(row * PAD + col) << 1));
                bf[j][0] = r4[0]; bf[j][1] = r4[1];
                bf[j + 1][0] = r4[2]; bf[j + 1][1] = r4[3];
            }
#pragma unroll
            for (int i = 0; i < MF; i++)
#pragma unroll
                for (int j = 0; j < NF; j++)
                    mma_f16(acc[i][j], af[i], bf[j]);
        }
    };

    const int ktiles = K / BK;
    ldgsts(0, 0);
    CP_COMMIT();
    if (ktiles > 1) ldgsts(1, 1);
    CP_COMMIT();
    for (int kt = 0; kt < ktiles; kt++) {
        if (kt + 1 < ktiles) { CP_WAIT1(); } else { CP_WAIT0(); }
        __syncthreads();
        if (kt + 2 < ktiles) ldgsts(kt + 2, (kt + 2) % 3);
        CP_COMMIT();
        compute(kt % 3);
    }

#pragma unroll
    for (int i = 0; i < MF; i++) {
        int r0 = m0 + warpM * WM + i * 16 + lr;
#pragma unroll
        for (int j = 0; j < NF; j++) {
            int c0 = n0 + warpN * WN + j * 8 + 2 * lc;
            float2 bv = bias ? *(const float2*)(bias + c0) : make_float2(0.f, 0.f);
            float x0 = acc[i][j][0] * alpha + bv.x;
            float x1 = acc[i][j][1] * alpha + bv.y;
            float x2 = acc[i][j][2] * alpha + bv.x;
            float x3 = acc[i][j][3] * alpha + bv.y;
            if constexpr (CMODE == 1) {
                __half* C = (__half*)Cp;
                *(__half2*)(C + (size_t)r0 * ldc + c0) = __floats2half2_rn(x0, x1);
                *(__half2*)(C + (size_t)(r0 + 8) * ldc + c0) = __floats2half2_rn(x2, x3);
            } else {
                float* C = (float*)Cp;
                *(float2*)(C + (size_t)r0 * ldc + c0) = make_float2(x0, x1);
                *(float2*)(C + (size_t)(r0 + 8) * ldc + c0) = make_float2(x2, x3);
            }
        }
    }
}

// ---------------- projection wrappers ----------------
__global__ void __launch_bounds__(256, 2) k_proj3(
    const __half* __restrict__ xq, const __half* __restrict__ xk, const __half* __restrict__ xv,
    const __half* __restrict__ wq, const __half* __restrict__ wk, const __half* __restrict__ wv,
    const float* __restrict__ bq, const float* __restrict__ bk, const float* __restrict__ bv,
    __half* __restrict__ qh, __half* __restrict__ kh, __half* __restrict__ vh)
{
    const __half* A; const __half* W; const float* bias; __half* C;
    if (blockIdx.z == 0)      { A = xq; W = wq; bias = bq; C = qh; }
    else if (blockIdx.z == 1) { A = xk; W = wk; bias = bk; C = kh; }
    else                      { A = xv; W = wv; bias = bv; C = vh; }
    mm_core<128, 2, 4, 1>(A, E_DIM, W, E_DIM, C, E_DIM, bias, 1.f, E_DIM,
                          blockIdx.y * 128, blockIdx.x * 128);
}

// ---------------------------------------------------------------------------
// Merged final wave: proj blocks + avg blocks (independent, overlapped).
// ---------------------------------------------------------------------------
#define NPROJ 256   // (E/128) * (MB/128)

__global__ void __launch_bounds__(256, 2) k_avg_proj(
    const __half* __restrict__ ctxh, const __half* __restrict__ wo,
    const float* __restrict__ bo, float* __restrict__ out,
    const __half* __restrict__ ptil, const float* __restrict__ zinv,
    float* __restrict__ avgw)
{
    const int bidx = blockIdx.x;
    if (bidx < NPROJ) {
        mm_core<128, 2, 4, 0>(ctxh, E_DIM, wo, E_DIM, out, E_DIM, bo, 1.f, E_DIM,
                              (bidx >> 3) * 128, (bidx & 7) * 128);
        return;
    }

    const int j = bidx - NPROJ;
    const int t = j & (T_DIM - 1);
    const int b = j >> 11;
    const int tid = threadIdx.x;

    float inv[H_DIM];
#pragma unroll
    for (int h = 0; h < H_DIM; h++)
        inv[h] = __ldg(zinv + (size_t)(b * H_DIM + h) * T_DIM + t);

    float acc[8];
#pragma unroll
    for (int i = 0; i < 8; i++) acc[i] = 0.f;

    uint4 u[H_DIM];
#pragma unroll
    for (int h = 0; h < H_DIM; h++)
        u[h] = *(const uint4*)(ptil + ((size_t)(b * H_DIM + h) * T_DIM + t) * S_DIM + tid * 8);

#pragma unroll
    for (int h = 0; h < H_DIM; h++) {
        const __half2* hp = (const __half2*)&u[h];
#pragma unroll
        for (int q = 0; q < 4; q++) {
            float2 f = __half22float2(hp[q]);
            acc[2 * q]     += f.x * inv[h];
            acc[2 * q + 1] += f.y * inv[h];
        }
    }

    const float invH = 1.f / (float)H_DIM;
    float* arow = avgw + ((size_t)b * T_DIM + t) * S_DIM + tid * 8;
    float4 o0 = {acc[0] * invH, acc[1] * invH, acc[2] * invH, acc[3] * invH};
    float4 o1 = {acc[4] * invH, acc[5] * invH, acc[6] * invH, acc[7] * invH};
    *(float4*)(arow) = o0;
    *(float4*)(arow + 4) = o1;
}

// ---------------------------------------------------------------------------
// Fused attention (R14 structure): QK^T + exp + p~ store + Z + (p~ @ V).
// 256 threads = 8 warps, warpM=4 x warpN=2, q A-frags hoisted. 32 s-chunks.
// p~ gmem store moved AFTER mma2 (overlaps next chunk's cp.async wait).
// ---------------------------------------------------------------------------
#define ACH 64
#define NCHK (S_DIM / ACH)     // 32
#define QOFF 0
#define QSZ  (128 * 72 * 2)            // 18432
#define KOFF QSZ                        // 18432
#define KSZ  (64 * 72 * 2)             // 9216 per buf, 3 bufs
#define VOFF (KOFF + 3 * KSZ)          // 46080
#define VSZ  (64 * 72 * 2)             // 9216 per buf, 3 bufs
#define POFF (VOFF + 3 * VSZ)          // 73728
#define PSZ  (128 * 72 * 2)            // 18432
#define ZOFF (POFF + PSZ)              // 92160
#define SM_ATTN (ZOFF + 128 * 2 * 4)   // 93184

#define EXP2_SCALE 0.18033688011112042f

__global__ void __launch_bounds__(256) k_attn(
    const __half* __restrict__ qh, const __half* __restrict__ kh,
    const __half* __restrict__ vt, __half* __restrict__ ptil,
    float* __restrict__ zinv, __half* __restrict__ ctx)
{
    extern __shared__ __align__(16) char dsm[];
    const uint32_t smb = smem_u32(dsm);
    float* zred = (float*)(dsm + ZOFF);   // [128][2]

    const int tid = threadIdx.x;
    const int wid = tid >> 5;
    const int lane = tid & 31;
    const int lr = lane >> 2, lc = lane & 3;
    const int warpM = wid & 3;            // 4
    const int warpN = wid >> 2;           // 2
    const int z  = blockIdx.x;
    const int t0 = blockIdx.y * 128;
    const int b = z >> 4, h = z & 15;

    const __half* qptr = qh + (size_t)b * E_DIM + h * HD_DIM;
    const __half* kptr = kh + (size_t)b * E_DIM + h * HD_DIM;
    const __half* vptr = vt + (size_t)z * HD_DIM * S_DIM;
    __half* pout = ptil + ((size_t)z * T_DIM + t0) * S_DIM;

    auto ldgK = [&](int c) {
        const int s0 = c * ACH;
        const uint32_t kb = smb + KOFF + (uint32_t)(c % 3) * KSZ;
#pragma unroll
        for (int i = 0; i < 2; i++) {
            int ch = tid + i * 256, r = ch >> 3, cc = (ch & 7) * 8;
            cp16(kb + (uint32_t)(r * 72 + cc) * 2,
                 kptr + (size_t)(s0 + r) * LDQ + cc);
        }
    };
    auto ldgV = [&](int c) {
        const int s0 = c * ACH;
        const uint32_t vb = smb + VOFF + (uint32_t)(c % 3) * VSZ;
#pragma unroll
        for (int i = 0; i < 2; i++) {
            int ch = tid + i * 256, r = ch >> 3, cc = (ch & 7) * 8;
            cp16(vb + (uint32_t)(r * 72 + cc) * 2,
                 vptr + (size_t)r * S_DIM + s0 + cc);
        }
    };

#pragma unroll
    for (int i = 0; i < 4; i++) {
        int ch = tid + i * 256, r = ch >> 3, cc = (ch & 7) * 8;
        cp16(smb + QOFF + (uint32_t)(r * 72 + cc) * 2,
             qptr + (size_t)(t0 + r) * LDQ + cc);
    }
    ldgK(0); ldgV(0);
    CP_COMMIT();
    ldgK(1); ldgV(1);
    CP_COMMIT();

    uint32_t afq[4][2][4];
    float acc2[2][4][4];
#pragma unroll
    for (int i = 0; i < 2; i++)
#pragma unroll
        for (int j = 0; j < 4; j++)
#pragma unroll
            for (int q = 0; q < 4; q++) acc2[i][j][q] = 0.f;
    float z0[2] = {0.f, 0.f}, z1[2] = {0.f, 0.f};

    for (int c = 0; c < NCHK; c++) {
        if (c + 1 < NCHK) { CP_WAIT1(); } else { CP_WAIT0(); }
        __syncthreads();

        if (c == 0) {
#pragma unroll
            for (int ks = 0; ks < 4; ks++)
#pragma unroll
                for (int i = 0; i < 2; i++) {
                    uint32_t off = (uint32_t)((warpM * 32 + i * 16 + (lane & 15)) * 72 +
                                              ks * 16 + ((lane >> 4) << 3));
                    ldm_x4(afq[ks][i], smb + QOFF + (off << 1));
                }
        }

        if (c + 2 < NCHK) { ldgK(c + 2); ldgV(c + 2); }
        CP_COMMIT();

        const uint32_t kb = smb + KOFF + (uint32_t)(c % 3) * KSZ;
        const uint32_t vb = smb + VOFF + (uint32_t)(c % 3) * VSZ;
        const int s0 = c * ACH;

        float acc1[2][4][4];
#pragma unroll
        for (int i = 0; i < 2; i++)
#pragma unroll
            for (int j = 0; j < 4; j++)
#pragma unroll
                for (int q = 0; q < 4; q++) acc1[i][j][q] = 0.f;

#pragma unroll
        for (int ks = 0; ks < 4; ks++) {
            const int khc = ks * 16;
            uint32_t bf[4][2];
#pragma unroll
            for (int j = 0; j < 4; j += 2) {
                int row = warpN * 32 + (j + (lane >> 4)) * 8 + (lane & 7);
                int col = khc + ((lane >> 3) & 1) * 8;
                uint32_t r4[4];
                ldm_x4(r4, kb + ((uint32_t)(row * 72 + col) << 1));
                bf[j][0] = r4[0]; bf[j][1] = r4[1];
                bf[j + 1][0] = r4[2]; bf[j + 1][1] = r4[3];
            }
#pragma unroll
            for (int i = 0; i < 2; i++)
#pragma unroll
                for (int j = 0; j < 4; j++)
                    mma_f16(acc1[i][j], afq[ks][i], bf[j]);
        }

#pragma unroll
        for (int i = 0; i < 2; i++) {
            int rl0 = warpM * 32 + i * 16 + lr;
#pragma unroll
            for (int j = 0; j < 4; j++) {
                int c0 = warpN * 32 + j * 8 + 2 * lc;
                float x0 = ex2(acc1[i][j][0] * EXP2_SCALE);
                float x1 = ex2(acc1[i][j][1] * EXP2_SCALE);
                float x2 = ex2(acc1[i][j][2] * EXP2_SCALE);
                float x3 = ex2(acc1[i][j][3] * EXP2_SCALE);
                z0[i] += x0 + x1;
                z1[i] += x2 + x3;
                *(__half2*)(dsm + POFF + (uint32_t)(rl0 * 72 + c0) * 2) =
                    __floats2half2_rn(x0, x1);
                *(__half2*)(dsm + POFF + (uint32_t)((rl0 + 8) * 72 + c0) * 2) =
                    __floats2half2_rn(x2, x3);
            }
        }
        __syncthreads();   // p tile visible

        // ---- mma2 first (tensor work issues immediately after sync) ----
#pragma unroll
        for (int ks = 0; ks < 4; ks++) {
            const int khc = ks * 16;
            uint32_t af[2][4], bf[4][2];
#pragma unroll
            for (int i = 0; i < 2; i++) {
                uint32_t off = (uint32_t)((warpM * 32 + i * 16 + (lane & 15)) * 72 +
                                          khc + ((lane >> 4) << 3));
                ldm_x4(af[i], smb + POFF + (off << 1));
            }
#pragma unroll
            for (int j = 0; j < 4; j += 2) {
                int row = warpN * 32 + (j + (lane >> 4)) * 8 + (lane & 7);
                int col = khc + ((lane >> 3) & 1) * 8;
                uint32_t r4[4];
                ldm_x4(r4, vb + ((uint32_t)(row * 72 + col) << 1));
                bf[j][0] = r4[0]; bf[j][1] = r4[1];
                bf[j + 1][0] = r4[2]; bf[j + 1][1] = r4[3];
            }
#pragma unroll
            for (int i = 0; i < 2; i++)
#pragma unroll
                for (int j = 0; j < 4; j++)
                    mma_f16(acc2[i][j], af[i], bf[j]);
        }

        // ---- coalesced p~ gmem store (drains under next chunk's wait) ----
#pragma unroll
        for (int i = 0; i < 4; i++) {
            int idx = tid + i * 256;
            int row = idx >> 3, col8 = (idx & 7) * 8;
            uint4 v = *(const uint4*)(dsm + POFF + (uint32_t)(row * 72 + col8) * 2);
            *(uint4*)(pout + (size_t)row * S_DIM + s0 + col8) = v;
        }
    }

#pragma unroll
    for (int i = 0; i < 2; i++) {
        z0[i] += __shfl_xor_sync(0xffffffffu, z0[i], 1);
        z0[i] += __shfl_xor_sync(0xffffffffu, z0[i], 2);
        z1[i] += __shfl_xor_sync(0xffffffffu, z1[i], 1);
        z1[i] += __shfl_xor_sync(0xffffffffu, z1[i], 2);
    }
    if (lc == 0) {
#pragma unroll
        for (int i = 0; i < 2; i++) {
            int rl0 = warpM * 32 + i * 16 + lr;
            zred[rl0 * 2 + warpN] = z0[i];
            zred[(rl0 + 8) * 2 + warpN] = z1[i];
        }
    }
    __syncthreads();

    if (tid < 128) {
        float Z = zred[tid * 2] + zred[tid * 2 + 1];
        zinv[(size_t)z * T_DIM + t0 + tid] = 1.f / Z;
    }

#pragma unroll
    for (int i = 0; i < 2; i++) {
        int rl0 = warpM * 32 + i * 16 + lr;
        float inv0 = 1.f / (zred[rl0 * 2] + zred[rl0 * 2 + 1]);
        float inv1 = 1.f / (zred[(rl0 + 8) * 2] + zred[(rl0 + 8) * 2 + 1]);
#pragma unroll
        for (int j = 0; j < 4; j++) {
            int c0 = warpN * 32 + j * 8 + 2 * lc;
            __half* d0 = ctx + ((size_t)(t0 + rl0) * B_DIM + b) * E_DIM + h * HD_DIM + c0;
            __half* d1 = ctx + ((size_t)(t0 + rl0 + 8) * B_DIM + b) * E_DIM + h * HD_DIM + c0;
            *(__half2*)d0 = __floats2half2_rn(acc2[i][j][0] * inv0, acc2[i][j][1] * inv0);
            *(__half2*)d1 = __floats2half2_rn(acc2[i][j][2] * inv1, acc2[i][j][3] * inv1);
        }
    }
}

// ---------------- single batched fp32 -> fp16 convert (7 tensors) ----------
__global__ void __launch_bounds__(256) k_cvt7(
    const float* __restrict__ i0, const float* __restrict__ i1, const float* __restrict__ i2,
    const float* __restrict__ w0, const float* __restrict__ w1,
    const float* __restrict__ w2, const float* __restrict__ w3,
    __half* __restrict__ o0, __half* __restrict__ o1, __half* __restrict__ o2,
    __half* __restrict__ p0, __half* __restrict__ p1,
    __half* __restrict__ p2, __half* __restrict__ p3,
    int n_in, int n_w)
{
    const float* x; __half* y; int n;
    switch (blockIdx.z) {
        case 0: x = i0; y = o0; n = n_in; break;
        case 1: x = i1; y = o1; n = n_in; break;
        case 2: x = i2; y = o2; n = n_in; break;
        case 3: x = w0; y = p0; n = n_w; break;
        case 4: x = w1; y = p1; n = n_w; break;
        case 5: x = w2; y = p2; n = n_w; break;
        default: x = w3; y = p3; n = n_w; break;
    }
    int i = (blockIdx.x * 256 + threadIdx.x) * 8;
    if (i < n) {
        float4 v0 = *(const float4*)(x + i);
        float4 v1 = *(const float4*)(x + i + 4);
        union { __half2 h[4]; uint4 u; } p;
        p.h[0] = __floats2half2_rn(v0.x, v0.y);
        p.h[1] = __floats2half2_rn(v0.z, v0.w);
        p.h[2] = __floats2half2_rn(v1.x, v1.y);
        p.h[3] = __floats2half2_rn(v1.z, v1.w);
        *(uint4*)(y + i) = p.u;
    }
}

// V transpose fp16
__global__ void __launch_bounds__(256) k_transpose_v(
    const __half* __restrict__ v, __half* __restrict__ vt)
{
    __shared__ __half t[32][34];
    int z = blockIdx.z, b = z >> 4, h = z & 15;
    int s0 = blockIdx.x * 32, d0 = blockIdx.y * 32;
    int lx = threadIdx.x & 31, ly = threadIdx.x >> 5;
#pragma unroll
    for (int i = 0; i < 32; i += 8) {
        int s = s0 + ly + i;
        t[ly + i][lx] = v[(size_t)(s * B_DIM + b) * E_DIM + h * HD_DIM + d0 + lx];
    }
    __syncthreads();
#pragma unroll
    for (int i = 0; i < 32; i += 8) {
        int d = d0 + ly + i;
        vt[((size_t)z * HD_DIM + d) * S_DIM + s0 + lx] = t[lx][ly + i];
    }
}

// ---------------------------------------------------------------------------
extern "C" void kernel_launch(void* const* d_in, const int* in_sizes, int n_in,
                              void* d_out, int out_size)
{
    const float* query = (const float*)d_in[0];
    const float* key   = (const float*)d_in[1];
    const float* value = (const float*)d_in[2];
    const float* Wq = (const float*)d_in[3];
    const float* bq = (const float*)d_in[4];
    const float* Wk = (const float*)d_in[5];
    const float* bk = (const float*)d_in[6];
    const float* Wv = (const float*)d_in[7];
    const float* bv = (const float*)d_in[8];
    const float* Wo = (const float*)d_in[9];
    const float* bo = (const float*)d_in[10];

    float* out  = (float*)d_out;
    float* avgw = out + (size_t)MB_DIM * E_DIM;

    __half *xq, *xk, *xv, *wq, *wk, *wv, *wo, *qh, *kh, *vh, *ctxh, *vt, *pt;
    float *zi;
    cudaGetSymbolAddress((void**)&xq,   g_xq);
    cudaGetSymbolAddress((void**)&xk,   g_xk);
    cudaGetSymbolAddress((void**)&xv,   g_xv);
    cudaGetSymbolAddress((void**)&wq,   g_wq);
    cudaGetSymbolAddress((void**)&wk,   g_wk);
    cudaGetSymbolAddress((void**)&wv,   g_wv);
    cudaGetSymbolAddress((void**)&wo,   g_wo);
    cudaGetSymbolAddress((void**)&qh,   g_qh);
    cudaGetSymbolAddress((void**)&kh,   g_kh);
    cudaGetSymbolAddress((void**)&vh,   g_vh);
    cudaGetSymbolAddress((void**)&ctxh, g_ctxh);
    cudaGetSymbolAddress((void**)&vt,   g_vt);
    cudaGetSymbolAddress((void**)&pt,   g_ptil);
    cudaGetSymbolAddress((void**)&zi,   g_zinv);

    const int SM_P3 = 3 * (128 + 128) * 72 * 2;   // 110592
    cudaFuncSetAttribute(k_proj3,    cudaFuncAttributeMaxDynamicSharedMemorySize, SM_P3);
    cudaFuncSetAttribute(k_avg_proj, cudaFuncAttributeMaxDynamicSharedMemorySize, SM_P3);
    cudaFuncSetAttribute(k_attn,     cudaFuncAttributeMaxDynamicSharedMemorySize, SM_ATTN);

    const int NXE = MB_DIM * E_DIM;   // 4M
    const int NWW = E_DIM * E_DIM;    // 1M
    dim3 gc(NXE / 2048, 1, 7);
    k_cvt7<<<gc, 256>>>(query, key, value, Wq, Wk, Wv, Wo,
                        xq, xk, xv, wq, wk, wv, wo, NXE, NWW);

    dim3 gp3(E_DIM / 128, MB_DIM / 128, 3);             // (8, 32, 3)
    k_proj3<<<gp3, 256, SM_P3>>>(xq, xk, xv, wq, wk, wv, bq, bk, bv, qh, kh, vh);

    dim3 gt(S_DIM / 32, HD_DIM / 32, B_DIM * H_DIM);    // (64, 2, 32)
    k_transpose_v<<<gt, 256>>>(vh, vt);

    dim3 gat(B_DIM * H_DIM, T_DIM / 128);               // (32, 16)
    k_attn<<<gat, 256, SM_ATTN>>>(qh, kh, vt, pt, zi, ctxh);

    k_avg_proj<<<NPROJ + MB_DIM, 256, SM_P3>>>(ctxh, wo, bo, out, pt, zi, avgw);
}

// round 17
// speedup vs baseline: 1.2047x; 1.0116x over previous
#include <cuda_runtime.h>
#include <cuda_fp16.h>
#include <cstdint>

#define T_DIM 2048
#define B_DIM 2
#define E_DIM 1024
#define H_DIM 16
#define HD_DIM 64
#define S_DIM 2048
#define MB_DIM (T_DIM * B_DIM)     // 4096
#define LDQ (B_DIM * E_DIM)        // 2048

// exp(x*0.125) == exp2(x * 0.125*log2(e)); scale folded into q projection.
#define EXP2_SCALE 0.18033688011112042f

// Static device scratch
__device__ __half g_xq[(size_t)MB_DIM * E_DIM];
__device__ __half g_xk[(size_t)MB_DIM * E_DIM];
__device__ __half g_xv[(size_t)MB_DIM * E_DIM];
__device__ __half g_wq[(size_t)E_DIM * E_DIM];
__device__ __half g_wk[(size_t)E_DIM * E_DIM];
__device__ __half g_wv[(size_t)E_DIM * E_DIM];
__device__ __half g_wo[(size_t)E_DIM * E_DIM];
__device__ __half g_qh[(size_t)MB_DIM * E_DIM];
__device__ __half g_kh[(size_t)MB_DIM * E_DIM];
__device__ __half g_vh[(size_t)MB_DIM * E_DIM];
__device__ __half g_ctxh[(size_t)MB_DIM * E_DIM];
__device__ __half g_vt[(size_t)B_DIM * H_DIM * HD_DIM * S_DIM];
__device__ __half g_ptil[(size_t)B_DIM * H_DIM * T_DIM * S_DIM];  // unnormalized exp scores
__device__ float  g_zinv[(size_t)B_DIM * H_DIM * T_DIM];          // per-row 1/Z

__device__ __forceinline__ uint32_t smem_u32(const void* p) {
    uint32_t a;
    asm("{ .reg .u64 t; cvta.to.shared.u64 t, %1; cvt.u32.u64 %0, t; }" : "=r"(a) : "l"(p));
    return a;
}
__device__ __forceinline__ void cp16(uint32_t dst, const void* src) {
    asm volatile("cp.async.ca.shared.global [%0], [%1], 16;" :: "r"(dst), "l"(src) : "memory");
}
#define CP_COMMIT() asm volatile("cp.async.commit_group;" ::: "memory")
#define CP_WAIT1()  asm volatile("cp.async.wait_group 1;" ::: "memory")
#define CP_WAIT0()  asm volatile("cp.async.wait_group 0;" ::: "memory")

__device__ __forceinline__ void ldm_x4(uint32_t r[4], uint32_t a) {
    asm volatile("ldmatrix.sync.aligned.m8n8.x4.shared.b16 {%0,%1,%2,%3}, [%4];"
        : "=r"(r[0]), "=r"(r[1]), "=r"(r[2]), "=r"(r[3]) : "r"(a));
}
__device__ __forceinline__ void mma_f16(float c[4], const uint32_t a[4], const uint32_t b[2]) {
    asm volatile(
        "mma.sync.aligned.m16n8k16.row.col.f32.f16.f16.f32 "
        "{%0,%1,%2,%3}, {%4,%5,%6,%7}, {%8,%9}, {%0,%1,%2,%3};"
        : "+f"(c[0]), "+f"(c[1]), "+f"(c[2]), "+f"(c[3])
        : "r"(a[0]), "r"(a[1]), "r"(a[2]), "r"(a[3]), "r"(b[0]), "r"(b[1]));
}
// ex2.approx.f32 — MUFU.EX2
__device__ __forceinline__ float ex2(float x) {
    float r;
    asm("ex2.approx.f32 %0, %1;" : "=f"(r) : "f"(x));
    return r;
}

// ---------------------------------------------------------------------------
// fp16 mma.sync GEMM core (projections). CMODE 0: fp32 out; 1: fp16 out.
// ---------------------------------------------------------------------------
template <int BN, int WARPS_M, int WARPS_N, int CMODE>
__device__ __forceinline__ void mm_core(
    const __half* __restrict__ A, int lda,
    const __half* __restrict__ B, int ldb,
    void* Cp, int ldc,
    const float* __restrict__ bias, float alpha, int K,
    int m0, int n0)
{
    constexpr int BM = 128, BK = 64, PAD = 72;
    constexpr int WM = BM / WARPS_M, WN = BN / WARPS_N;
    constexpr int MF = WM / 16, NF = WN / 8;
    constexpr int NCA = (BM * BK / 8) / 256;
    constexpr int NCB = (BN * BK / 8) / 256;
    constexpr uint32_t ASTG = BM * PAD * 2;
    constexpr uint32_t BSTG = BN * PAD * 2;
    constexpr uint32_t STG  = ASTG + BSTG;

    extern __shared__ __align__(16) char dsm[];

    const int tid = threadIdx.x;
    const int wid = tid >> 5;
    const int lane = tid & 31;
    const int lr = lane >> 2;
    const int lc = lane & 3;
    const int warpM = wid % WARPS_M;
    const int warpN = wid / WARPS_M;

    const uint32_t smb = smem_u32(dsm);

    float acc[MF][NF][4];
#pragma unroll
    for (int i = 0; i < MF; i++)
#pragma unroll
        for (int j = 0; j < NF; j++)
#pragma unroll
            for (int q = 0; q < 4; q++) acc[i][j][q] = 0.f;

    auto ldgsts = [&](int kt, int p) {
        const int k0 = kt * BK;
        const uint32_t ab = smb + (uint32_t)p * STG;
        const uint32_t bb = ab + ASTG;
#pragma unroll
        for (int i = 0; i < NCA; i++) {
            int ch = tid + i * 256, r = ch >> 3, c = (ch & 7) * 8;
            cp16(ab + (uint32_t)(r * PAD + c) * 2,
                 A + (size_t)(m0 + r) * lda + k0 + c);
        }
#pragma unroll
        for (int i = 0; i < NCB; i++) {
            int ch = tid + i * 256, r = ch >> 3, c = (ch & 7) * 8;
            cp16(bb + (uint32_t)(r * PAD + c) * 2,
                 B + (size_t)(n0 + r) * ldb + k0 + c);
        }
    };

    auto compute = [&](int p) {
        const uint32_t ab = smb + (uint32_t)p * STG;
        const uint32_t bb = ab + ASTG;
#pragma unroll
        for (int ks = 0; ks < BK / 16; ks++) {
            const int kh = ks * 16;
            uint32_t af[MF][4], bf[NF][2];
#pragma unroll
            for (int i = 0; i < MF; i++) {
                uint32_t off = (uint32_t)((warpM * WM + i * 16 + (lane & 15)) * PAD +
                                          kh + ((lane >> 4) << 3));
                ldm_x4(af[i], ab + (off << 1));
            }
#pragma unroll
            for (int j = 0; j < NF; j += 2) {
                int row = warpN * WN + (j + (lane >> 4)) * 8 + (lane & 7);
                int col = kh + ((lane >> 3) & 1) * 8;
                uint32_t r4[4];
                ldm_x4(r4, bb + ((uint32_t)(row * PAD + col) << 1));
                bf[j][0] = r4[0]; bf[j][1] = r4[1];
                bf[j + 1][0] = r4[2]; bf[j + 1][1] = r4[3];
            }
#pragma unroll
            for (int i = 0; i < MF; i++)
#pragma unroll
                for (int j = 0; j < NF; j++)
                    mma_f16(acc[i][j], af[i], bf[j]);
        }
    };

    const int ktiles = K / BK;
    ldgsts(0, 0);
    CP_COMMIT();
    if (ktiles > 1) ldgsts(1, 1);
    CP_COMMIT();
    for (int kt = 0; kt < ktiles; kt++) {
        if (kt + 1 < ktiles) { CP_WAIT1(); } else { CP_WAIT0(); }
        __syncthreads();
        if (kt + 2 < ktiles) ldgsts(kt + 2, (kt + 2) % 3);
        CP_COMMIT();
        compute(kt % 3);
    }

#pragma unroll
    for (int i = 0; i < MF; i++) {
        int r0 = m0 + warpM * WM + i * 16 + lr;
#pragma unroll
        for (int j = 0; j < NF; j++) {
            int c0 = n0 + warpN * WN + j * 8 + 2 * lc;
            float2 bv = bias ? *(const float2*)(bias + c0) : make_float2(0.f, 0.f);
            float x0 = (acc[i][j][0] + bv.x) * alpha;
            float x1 = (acc[i][j][1] + bv.y) * alpha;
            float x2 = (acc[i][j][2] + bv.x) * alpha;
            float x3 = (acc[i][j][3] + bv.y) * alpha;
            if constexpr (CMODE == 1) {
                __half* C = (__half*)Cp;
                *(__half2*)(C + (size_t)r0 * ldc + c0) = __floats2half2_rn(x0, x1);
                *(__half2*)(C + (size_t)(r0 + 8) * ldc + c0) = __floats2half2_rn(x2, x3);
            } else {
                float* C = (float*)Cp;
                *(float2*)(C + (size_t)r0 * ldc + c0) = make_float2(x0, x1);
                *(float2*)(C + (size_t)(r0 + 8) * ldc + c0) = make_float2(x2, x3);
            }
        }
    }
}

// ---------------- projection wrappers ----------------
// q projection carries alpha = EXP2_SCALE so k_attn's exp is a bare ex2().
__global__ void __launch_bounds__(256, 2) k_proj3(
    const __half* __restrict__ xq, const __half* __restrict__ xk, const __half* __restrict__ xv,
    const __half* __restrict__ wq, const __half* __restrict__ wk, const __half* __restrict__ wv,
    const float* __restrict__ bq, const float* __restrict__ bk, const float* __restrict__ bv,
    __half* __restrict__ qh, __half* __restrict__ kh, __half* __restrict__ vh)
{
    const __half* A; const __half* W; const float* bias; __half* C; float alpha;
    if (blockIdx.z == 0)      { A = xq; W = wq; bias = bq; C = qh; alpha = EXP2_SCALE; }
    else if (blockIdx.z == 1) { A = xk; W = wk; bias = bk; C = kh; alpha = 1.f; }
    else                      { A = xv; W = wv; bias = bv; C = vh; alpha = 1.f; }
    mm_core<128, 2, 4, 1>(A, E_DIM, W, E_DIM, C, E_DIM, bias, alpha, E_DIM,
                          blockIdx.y * 128, blockIdx.x * 128);
}

// ---------------------------------------------------------------------------
// Merged final wave: proj blocks + avg blocks (independent, overlapped).
// ---------------------------------------------------------------------------
#define NPROJ 256   // (E/128) * (MB/128)

__global__ void __launch_bounds__(256, 2) k_avg_proj(
    const __half* __restrict__ ctxh, const __half* __restrict__ wo,
    const float* __restrict__ bo, float* __restrict__ out,
    const __half* __restrict__ ptil, const float* __restrict__ zinv,
    float* __restrict__ avgw)
{
    const int bidx = blockIdx.x;
    if (bidx < NPROJ) {
        mm_core<128, 2, 4, 0>(ctxh, E_DIM, wo, E_DIM, out, E_DIM, bo, 1.f, E_DIM,
                              (bidx >> 3) * 128, (bidx & 7) * 128);
        return;
    }

    const int j = bidx - NPROJ;
    const int t = j & (T_DIM - 1);
    const int b = j >> 11;
    const int tid = threadIdx.x;

    float inv[H_DIM];
#pragma unroll
    for (int h = 0; h < H_DIM; h++)
        inv[h] = __ldg(zinv + (size_t)(b * H_DIM + h) * T_DIM + t);

    float acc[8];
#pragma unroll
    for (int i = 0; i < 8; i++) acc[i] = 0.f;

    uint4 u[H_DIM];
#pragma unroll
    for (int h = 0; h < H_DIM; h++)
        u[h] = *(const uint4*)(ptil + ((size_t)(b * H_DIM + h) * T_DIM + t) * S_DIM + tid * 8);

#pragma unroll
    for (int h = 0; h < H_DIM; h++) {
        const __half2* hp = (const __half2*)&u[h];
#pragma unroll
        for (int q = 0; q < 4; q++) {
            float2 f = __half22float2(hp[q]);
            acc[2 * q]     += f.x * inv[h];
            acc[2 * q + 1] += f.y * inv[h];
        }
    }

    const float invH = 1.f / (float)H_DIM;
    float* arow = avgw + ((size_t)b * T_DIM + t) * S_DIM + tid * 8;
    float4 o0 = {acc[0] * invH, acc[1] * invH, acc[2] * invH, acc[3] * invH};
    float4 o1 = {acc[4] * invH, acc[5] * invH, acc[6] * invH, acc[7] * invH};
    *(float4*)(arow) = o0;
    *(float4*)(arow + 4) = o1;
}

// ---------------------------------------------------------------------------
// Fused attention: QK^T (q pre-scaled) + ex2 + p~ store + Z + (p~ @ V).
// 256 threads = 8 warps, warpM=4 x warpN=2, q A-frags hoisted. 32 s-chunks.
// ---------------------------------------------------------------------------
#define ACH 64
#define NCHK (S_DIM / ACH)     // 32
#define QOFF 0
#define QSZ  (128 * 72 * 2)            // 18432
#define KOFF QSZ                        // 18432
#define KSZ  (64 * 72 * 2)             // 9216 per buf, 3 bufs
#define VOFF (KOFF + 3 * KSZ)          // 46080
#define VSZ  (64 * 72 * 2)             // 9216 per buf, 3 bufs
#define POFF (VOFF + 3 * VSZ)          // 73728
#define PSZ  (128 * 72 * 2)            // 18432
#define ZOFF (POFF + PSZ)              // 92160
#define SM_ATTN (ZOFF + 128 * 2 * 4)   // 93184

__global__ void __launch_bounds__(256) k_attn(
    const __half* __restrict__ qh, const __half* __restrict__ kh,
    const __half* __restrict__ vt, __half* __restrict__ ptil,
    float* __restrict__ zinv, __half* __restrict__ ctx)
{
    extern __shared__ __align__(16) char dsm[];
    const uint32_t smb = smem_u32(dsm);
    float* zred = (float*)(dsm + ZOFF);   // [128][2]

    const int tid = threadIdx.x;
    const int wid = tid >> 5;
    const int lane = tid & 31;
    const int lr = lane >> 2, lc = lane & 3;
    const int warpM = wid & 3;            // 4
    const int warpN = wid >> 2;           // 2
    const int z  = blockIdx.x;
    const int t0 = blockIdx.y * 128;
    const int b = z >> 4, h = z & 15;

    const __half* qptr = qh + (size_t)b * E_DIM + h * HD_DIM;
    const __half* kptr = kh + (size_t)b * E_DIM + h * HD_DIM;
    const __half* vptr = vt + (size_t)z * HD_DIM * S_DIM;
    __half* pout = ptil + ((size_t)z * T_DIM + t0) * S_DIM;

    auto ldgK = [&](int c) {
        const int s0 = c * ACH;
        const uint32_t kb = smb + KOFF + (uint32_t)(c % 3) * KSZ;
#pragma unroll
        for (int i = 0; i < 2; i++) {
            int ch = tid + i * 256, r = ch >> 3, cc = (ch & 7) * 8;
            cp16(kb + (uint32_t)(r * 72 + cc) * 2,
                 kptr + (size_t)(s0 + r) * LDQ + cc);
        }
    };
    auto ldgV = [&](int c) {
        const int s0 = c * ACH;
        const uint32_t vb = smb + VOFF + (uint32_t)(c % 3) * VSZ;
#pragma unroll
        for (int i = 0; i < 2; i++) {
            int ch = tid + i * 256, r = ch >> 3, cc = (ch & 7) * 8;
            cp16(vb + (uint32_t)(r * 72 + cc) * 2,
                 vptr + (size_t)r * S_DIM + s0 + cc);
        }
    };

#pragma unroll
    for (int i = 0; i < 4; i++) {
        int ch = tid + i * 256, r = ch >> 3, cc = (ch & 7) * 8;
        cp16(smb + QOFF + (uint32_t)(r * 72 + cc) * 2,
             qptr + (size_t)(t0 + r) * LDQ + cc);
    }
    ldgK(0); ldgV(0);
    CP_COMMIT();
    ldgK(1); ldgV(1);
    CP_COMMIT();

    uint32_t afq[4][2][4];
    float acc2[2][4][4];
#pragma unroll
    for (int i = 0; i < 2; i++)
#pragma unroll
        for (int j = 0; j < 4; j++)
#pragma unroll
            for (int q = 0; q < 4; q++) acc2[i][j][q] = 0.f;
    float z0[2] = {0.f, 0.f}, z1[2] = {0.f, 0.f};

    for (int c = 0; c < NCHK; c++) {
        if (c + 1 < NCHK) { CP_WAIT1(); } else { CP_WAIT0(); }
        __syncthreads();

        if (c == 0) {
#pragma unroll
            for (int ks = 0; ks < 4; ks++)
#pragma unroll
                for (int i = 0; i < 2; i++) {
                    uint32_t off = (uint32_t)((warpM * 32 + i * 16 + (lane & 15)) * 72 +
                                              ks * 16 + ((lane >> 4) << 3));
                    ldm_x4(afq[ks][i], smb + QOFF + (off << 1));
                }
        }

        if (c + 2 < NCHK) { ldgK(c + 2); ldgV(c + 2); }
        CP_COMMIT();

        const uint32_t kb = smb + KOFF + (uint32_t)(c % 3) * KSZ;
        const uint32_t vb = smb + VOFF + (uint32_t)(c % 3) * VSZ;
        const int s0 = c * ACH;

        float acc1[2][4][4];
#pragma unroll
        for (int i = 0; i < 2; i++)
#pragma unroll
            for (int j = 0; j < 4; j++)
#pragma unroll
                for (int q = 0; q < 4; q++) acc1[i][j][q] = 0.f;

#pragma unroll
        for (int ks = 0; ks < 4; ks++) {
            const int khc = ks * 16;
            uint32_t bf[4][2];
#pragma unroll
            for (int j = 0; j < 4; j += 2) {
                int row = warpN * 32 + (j + (lane >> 4)) * 8 + (lane & 7);
                int col = khc + ((lane >> 3) & 1) * 8;
                uint32_t r4[4];
                ldm_x4(r4, kb + ((uint32_t)(row * 72 + col) << 1));
                bf[j][0] = r4[0]; bf[j][1] = r4[1];
                bf[j + 1][0] = r4[2]; bf[j + 1][1] = r4[3];
            }
#pragma unroll
            for (int i = 0; i < 2; i++)
#pragma unroll
                for (int j = 0; j < 4; j++)
                    mma_f16(acc1[i][j], afq[ks][i], bf[j]);
        }

        // ---- bare ex2 (scale pre-folded into q) + Z + STS p~ ----
#pragma unroll
        for (int i = 0; i < 2; i++) {
            int rl0 = warpM * 32 + i * 16 + lr;
#pragma unroll
            for (int j = 0; j < 4; j++) {
                int c0 = warpN * 32 + j * 8 + 2 * lc;
                float x0 = ex2(acc1[i][j][0]);
                float x1 = ex2(acc1[i][j][1]);
                float x2 = ex2(acc1[i][j][2]);
                float x3 = ex2(acc1[i][j][3]);
                z0[i] += x0 + x1;
                z1[i] += x2 + x3;
                *(__half2*)(dsm + POFF + (uint32_t)(rl0 * 72 + c0) * 2) =
                    __floats2half2_rn(x0, x1);
                *(__half2*)(dsm + POFF + (uint32_t)((rl0 + 8) * 72 + c0) * 2) =
                    __floats2half2_rn(x2, x3);
            }
        }
        __syncthreads();   // p tile visible

        // ---- mma2 ----
#pragma unroll
        for (int ks = 0; ks < 4; ks++) {
            const int khc = ks * 16;
            uint32_t af[2][4], bf[4][2];
#pragma unroll
            for (int i = 0; i < 2; i++) {
                uint32_t off = (uint32_t)((warpM * 32 + i * 16 + (lane & 15)) * 72 +
                                          khc + ((lane >> 4) << 3));
                ldm_x4(af[i], smb + POFF + (off << 1));
            }
#pragma unroll
            for (int j = 0; j < 4; j += 2) {
                int row = warpN * 32 + (j + (lane >> 4)) * 8 + (lane & 7);
                int col = khc + ((lane >> 3) & 1) * 8;
                uint32_t r4[4];
                ldm_x4(r4, vb + ((uint32_t)(row * 72 + col) << 1));
                bf[j][0] = r4[0]; bf[j][1] = r4[1];
                bf[j + 1][0] = r4[2]; bf[j + 1][1] = r4[3];
            }
#pragma unroll
            for (int i = 0; i < 2; i++)
#pragma unroll
                for (int j = 0; j < 4; j++)
                    mma_f16(acc2[i][j], af[i], bf[j]);
        }

        // ---- coalesced p~ gmem store ----
#pragma unroll
        for (int i = 0; i < 4; i++) {
            int idx = tid + i * 256;
            int row = idx >> 3, col8 = (idx & 7) * 8;
            uint4 v = *(const uint4*)(dsm + POFF + (uint32_t)(row * 72 + col8) * 2);
            *(uint4*)(pout + (size_t)row * S_DIM + s0 + col8) = v;
        }
    }

#pragma unroll
    for (int i = 0; i < 2; i++) {
        z0[i] += __shfl_xor_sync(0xffffffffu, z0[i], 1);
        z0[i] += __shfl_xor_sync(0xffffffffu, z0[i], 2);
        z1[i] += __shfl_xor_sync(0xffffffffu, z1[i], 1);
        z1[i] += __shfl_xor_sync(0xffffffffu, z1[i], 2);
    }
    if (lc == 0) {
#pragma unroll
        for (int i = 0; i < 2; i++) {
            int rl0 = warpM * 32 + i * 16 + lr;
            zred[rl0 * 2 + warpN] = z0[i];
            zred[(rl0 + 8) * 2 + warpN] = z1[i];
        }
    }
    __syncthreads();

    if (tid < 128) {
        float Z = zred[tid * 2] + zred[tid * 2 + 1];
        zinv[(size_t)z * T_DIM + t0 + tid] = 1.f / Z;
    }

#pragma unroll
    for (int i = 0; i < 2; i++) {
        int rl0 = warpM * 32 + i * 16 + lr;
        float inv0 = 1.f / (zred[rl0 * 2] + zred[rl0 * 2 + 1]);
        float inv1 = 1.f / (zred[(rl0 + 8) * 2] + zred[(rl0 + 8) * 2 + 1]);
#pragma unroll
        for (int j = 0; j < 4; j++) {
            int c0 = warpN * 32 + j * 8 + 2 * lc;
            __half* d0 = ctx + ((size_t)(t0 + rl0) * B_DIM + b) * E_DIM + h * HD_DIM + c0;
            __half* d1 = ctx + ((size_t)(t0 + rl0 + 8) * B_DIM + b) * E_DIM + h * HD_DIM + c0;
            *(__half2*)d0 = __floats2half2_rn(acc2[i][j][0] * inv0, acc2[i][j][1] * inv0);
            *(__half2*)d1 = __floats2half2_rn(acc2[i][j][2] * inv1, acc2[i][j][3] * inv1);
        }
    }
}

// ---------------- single batched fp32 -> fp16 convert (7 tensors) ----------
__global__ void __launch_bounds__(256) k_cvt7(
    const float* __restrict__ i0, const float* __restrict__ i1, const float* __restrict__ i2,
    const float* __restrict__ w0, const float* __restrict__ w1,
    const float* __restrict__ w2, const float* __restrict__ w3,
    __half* __restrict__ o0, __half* __restrict__ o1, __half* __restrict__ o2,
    __half* __restrict__ p0, __half* __restrict__ p1,
    __half* __restrict__ p2, __half* __restrict__ p3,
    int n_in, int n_w)
{
    const float* x; __half* y; int n;
    switch (blockIdx.z) {
        case 0: x = i0; y = o0; n = n_in; break;
        case 1: x = i1; y = o1; n = n_in; break;
        case 2: x = i2; y = o2; n = n_in; break;
        case 3: x = w0; y = p0; n = n_w; break;
        case 4: x = w1; y = p1; n = n_w; break;
        case 5: x = w2; y = p2; n = n_w; break;
        default: x = w3; y = p3; n = n_w; break;
    }
    int i = (blockIdx.x * 256 + threadIdx.x) * 8;
    if (i < n) {
        float4 v0 = *(const float4*)(x + i);
        float4 v1 = *(const float4*)(x + i + 4);
        union { __half2 h[4]; uint4 u; } p;
        p.h[0] = __floats2half2_rn(v0.x, v0.y);
        p.h[1] = __floats2half2_rn(v0.z, v0.w);
        p.h[2] = __floats2half2_rn(v1.x, v1.y);
        p.h[3] = __floats2half2_rn(v1.z, v1.w);
        *(uint4*)(y + i) = p.u;
    }
}

// V transpose fp16
__global__ void __launch_bounds__(256) k_transpose_v(
    const __half* __restrict__ v, __half* __restrict__ vt)
{
    __shared__ __half t[32][34];
    int z = blockIdx.z, b = z >> 4, h = z & 15;
    int s0 = blockIdx.x * 32, d0 = blockIdx.y * 32;
    int lx = threadIdx.x & 31, ly = threadIdx.x >> 5;
#pragma unroll
    for (int i = 0; i < 32; i += 8) {
        int s = s0 + ly + i;
        t[ly + i][lx] = v[(size_t)(s * B_DIM + b) * E_DIM + h * HD_DIM + d0 + lx];
    }
    __syncthreads();
#pragma unroll
    for (int i = 0; i < 32; i += 8) {
        int d = d0 + ly + i;
        vt[((size_t)z * HD_DIM + d) * S_DIM + s0 + lx] = t[lx][ly + i];
    }
}

// ---------------------------------------------------------------------------
extern "C" void kernel_launch(void* const* d_in, const int* in_sizes, int n_in,
                              void* d_out, int out_size)
{
    const float* query = (const float*)d_in[0];
    const float* key   = (const float*)d_in[1];
    const float* value = (const float*)d_in[2];
    const float* Wq = (const float*)d_in[3];
    const float* bq = (const float*)d_in[4];
    const float* Wk = (const float*)d_in[5];
    const float* bk = (const float*)d_in[6];
    const float* Wv = (const float*)d_in[7];
    const float* bv = (const float*)d_in[8];
    const float* Wo = (const float*)d_in[9];
    const float* bo = (const float*)d_in[10];

    float* out  = (float*)d_out;
    float* avgw = out + (size_t)MB_DIM * E_DIM;

    __half *xq, *xk, *xv, *wq, *wk, *wv, *wo, *qh, *kh, *vh, *ctxh, *vt, *pt;
    float *zi;
    cudaGetSymbolAddress((void**)&xq,   g_xq);
    cudaGetSymbolAddress((void**)&xk,   g_xk);
    cudaGetSymbolAddress((void**)&xv,   g_xv);
    cudaGetSymbolAddress((void**)&wq,   g_wq);
    cudaGetSymbolAddress((void**)&wk,   g_wk);
    cudaGetSymbolAddress((void**)&wv,   g_wv);
    cudaGetSymbolAddress((void**)&wo,   g_wo);
    cudaGetSymbolAddress((void**)&qh,   g_qh);
    cudaGetSymbolAddress((void**)&kh,   g_kh);
    cudaGetSymbolAddress((void**)&vh,   g_vh);
    cudaGetSymbolAddress((void**)&ctxh, g_ctxh);
    cudaGetSymbolAddress((void**)&vt,   g_vt);
    cudaGetSymbolAddress((void**)&pt,   g_ptil);
    cudaGetSymbolAddress((void**)&zi,   g_zinv);

    const int SM_P3 = 3 * (128 + 128) * 72 * 2;   // 110592
    cudaFuncSetAttribute(k_proj3,    cudaFuncAttributeMaxDynamicSharedMemorySize, SM_P3);
    cudaFuncSetAttribute(k_avg_proj, cudaFuncAttributeMaxDynamicSharedMemorySize, SM_P3);
    cudaFuncSetAttribute(k_attn,     cudaFuncAttributeMaxDynamicSharedMemorySize, SM_ATTN);

    const int NXE = MB_DIM * E_DIM;   // 4M
    const int NWW = E_DIM * E_DIM;    // 1M
    dim3 gc(NXE / 2048, 1, 7);
    k_cvt7<<<gc, 256>>>(query, key, value, Wq, Wk, Wv, Wo,
                        xq, xk, xv, wq, wk, wv, wo, NXE, NWW);

    dim3 gp3(E_DIM / 128, MB_DIM / 128, 3);             // (8, 32, 3)
    k_proj3<<<gp3, 256, SM_P3>>>(xq, xk, xv, wq, wk, wv, bq, bk, bv, qh, kh, vh);

    dim3 gt(S_DIM / 32, HD_DIM / 32, B_DIM * H_DIM);    // (64, 2, 32)
    k_transpose_v<<<gt, 256>>>(vh, vt);

    dim3 gat(B_DIM * H_DIM, T_DIM / 128);               // (32, 16)
    k_attn<<<gat, 256, SM_ATTN>>>(qh, kh, vt, pt, zi, ctxh);

    k_avg_proj<<<NPROJ + MB_DIM, 256, SM_P3>>>(ctxh, wo, bo, out, pt, zi, avgw);
}